// round 8
// baseline (speedup 1.0000x reference)
#include <cuda_runtime.h>
#include <cuda_bf16.h>
#include <math.h>
#include <stdint.h>

#define NB   32
#define SEQL 512
#define DIM  256
#define S2   514
#define NTOK (NB * S2)
#define HID  1024
#define WD   1280
#define NSTEPS 6
#define EPSF 1e-9f

// planar bf16 hi/lo buffers (x = hi + lo, both bf16)
static __device__ __align__(256) __nv_bfloat16 g_flat_hi[NTOK * WD];
static __device__ __align__(256) __nv_bfloat16 g_flat_lo[NTOK * WD];
static __device__ __align__(256) __nv_bfloat16 g_cc_hi[NTOK * 2 * DIM];
static __device__ __align__(256) __nv_bfloat16 g_cc_lo[NTOK * 2 * DIM];
static __device__ __align__(256) __nv_bfloat16 g_inter_hi[NTOK * HID];
static __device__ __align__(256) __nv_bfloat16 g_inter_lo[NTOK * HID];
static __device__ __align__(256) float g_contents[NTOK * HID];
static __device__ __align__(256) float g_convOut[NTOK * DIM];   // init path only
static __device__ __align__(256) float g_seq[NTOK * DIM];
static __device__ float g_tsc[NTOK], g_tp[NTOK], g_ltp[NTOK];
static __device__ float g_active[NTOK], g_mask[NTOK], g_selp[NTOK], g_endm[NTOK];
static __device__ float g_mx;
// pre-transposed weights, planar: Wt[n*K+k] = W[k*N+n]
static __device__ __align__(256) __nv_bfloat16 g_convWt_hi[DIM * WD],   g_convWt_lo[DIM * WD];
static __device__ __align__(256) __nv_bfloat16 g_w1Wt_hi[HID * 2 * DIM], g_w1Wt_lo[HID * 2 * DIM];
static __device__ __align__(256) __nv_bfloat16 g_w2Wt_hi[HID * HID],    g_w2Wt_lo[HID * HID];
static __device__ __align__(256) __nv_bfloat16 g_itWt_hi[DIM * DIM],    g_itWt_lo[DIM * DIM];

__device__ __forceinline__ float geluf(float x) {
    float x3 = x * x * x;
    return 0.5f * x * (1.f + tanhf(0.7978845608028654f * (x + 0.044715f * x3)));
}
__device__ __forceinline__ void pack2(float x, unsigned short& h, unsigned short& l) {
    __nv_bfloat16 bh = __float2bfloat16(x);
    h = __bfloat16_as_ushort(bh);
    l = __bfloat16_as_ushort(__float2bfloat16(x - __bfloat162float(bh)));
}
__device__ __forceinline__ void st4p(__nv_bfloat16* H, __nv_bfloat16* L, float4 v) {
    ushort4 h, l;
    pack2(v.x, h.x, l.x); pack2(v.y, h.y, l.y);
    pack2(v.z, h.z, l.z); pack2(v.w, h.w, l.w);
    *(ushort4*)H = h; *(ushort4*)L = l;
}

__device__ __forceinline__ float blockReduceSum256(float v) {
    __shared__ float sh[33];
    int lane = threadIdx.x & 31, wid = threadIdx.x >> 5;
#pragma unroll
    for (int o = 16; o; o >>= 1) v += __shfl_down_sync(0xffffffffu, v, o);
    __syncthreads();
    if (lane == 0) sh[wid] = v;
    __syncthreads();
    if (wid == 0) {
        float t = (lane < 8) ? sh[lane] : 0.f;
#pragma unroll
        for (int o = 16; o; o >>= 1) t += __shfl_down_sync(0xffffffffu, t, o);
        if (lane == 0) sh[32] = t;
    }
    __syncthreads();
    return sh[32];
}

// ---------------- mma.sync helpers ----------------
__device__ __forceinline__ uint32_t s2u(const void* p) { return (uint32_t)__cvta_generic_to_shared(p); }
__device__ __forceinline__ void ldm4(uint32_t* r, uint32_t a) {
    asm volatile("ldmatrix.sync.aligned.m8n8.x4.shared.b16 {%0,%1,%2,%3}, [%4];"
                 : "=r"(r[0]), "=r"(r[1]), "=r"(r[2]), "=r"(r[3]) : "r"(a));
}
__device__ __forceinline__ void mma16816(float* c, const uint32_t* a, const uint32_t* b) {
    asm volatile("mma.sync.aligned.m16n8k16.row.col.f32.bf16.bf16.f32 "
                 "{%0,%1,%2,%3},{%4,%5,%6,%7},{%8,%9},{%0,%1,%2,%3};"
                 : "+f"(c[0]), "+f"(c[1]), "+f"(c[2]), "+f"(c[3])
                 : "r"(a[0]), "r"(a[1]), "r"(a[2]), "r"(a[3]), "r"(b[0]), "r"(b[1]));
}
__device__ __forceinline__ void cpasync16(uint32_t dst, const void* src, int srcsize) {
    asm volatile("cp.async.cg.shared.global [%0], [%1], 16, %2;"
                 :: "r"(dst), "l"(src), "r"(srcsize) : "memory");
}

// ---------------- GEMM: C[M,N] = (Ah+Al)@(Bh+Bl)^T + bias ----------------
// CTA 128x256, 512 threads (16 warps of 64x32), K-tile 64, 2-stage cp.async.
// Grid: x = N-tile (fast, shares A tile via L2), y = M-tile.
// A-plane staged loading keeps live regs ~96 (no spills at 128-reg cap).
// SCORE=1: no C store; epilogue computes tsc[row] = gelu(row)·scW + scb, atomicMax g_mx.
#define STG_BYTES 110592
#define ROWB 144
template <int ACT, int OUTP, int SCORE>
__global__ __launch_bounds__(512, 1) void mma_gemm(
    const __nv_bfloat16* __restrict__ Ah, const __nv_bfloat16* __restrict__ Al, int lda,
    const __nv_bfloat16* __restrict__ Bh, const __nv_bfloat16* __restrict__ Bl,
    const float* __restrict__ bias, void* __restrict__ C0, void* __restrict__ C1,
    int ldc, int M, int K,
    const float* __restrict__ scW, const float* __restrict__ scb)
{
    extern __shared__ char smem[];
    const uint32_t sbase = s2u(smem);
    const int tid = threadIdx.x, w = tid >> 5, lane = tid & 31;
    const int bm = blockIdx.y * 128, bn = blockIdx.x * 256;
    const int NK = K >> 6;
    const int m0 = (w & 1) * 64, n0w = (w >> 1) * 32;

    float acc[4][4][4];
#pragma unroll
    for (int i = 0; i < 4; i++)
#pragma unroll
        for (int j = 0; j < 4; j++)
#pragma unroll
            for (int e = 0; e < 4; e++) acc[i][j][e] = 0.f;

    auto fill = [&](int st, int kt) {
        int k0 = kt << 6;
#pragma unroll
        for (int q = 0; q < 12; q++) {
            int u = tid + q * 512;               // 6144 units of 16B
            const __nv_bfloat16* src;
            uint32_t dst;
            int sz = 16;
            if (u < 2048) {
                int plane = u >> 10, r = (u >> 3) & 127, c = u & 7;
                int gr = bm + r;
                if (gr >= M) { gr = 0; sz = 0; }
                src = (plane ? Al : Ah) + (size_t)gr * lda + k0 + c * 8;
                dst = sbase + st * STG_BYTES + plane * 18432 + r * ROWB + c * 16;
            } else {
                int v = u - 2048;
                int plane = v >> 11, r = (v >> 3) & 255, c = v & 7;
                src = (plane ? Bl : Bh) + (size_t)(bn + r) * K + k0 + c * 8;
                dst = sbase + st * STG_BYTES + 36864 + plane * 36864 + r * ROWB + c * 16;
            }
            cpasync16(dst, src, sz);
        }
        asm volatile("cp.async.commit_group;" ::: "memory");
    };

    fill(0, 0);
    for (int kt = 0; kt < NK; kt++) {
        if (kt + 1 < NK) {
            fill((kt + 1) & 1, kt + 1);
            asm volatile("cp.async.wait_group 1;" ::: "memory");
        } else {
            asm volatile("cp.async.wait_group 0;" ::: "memory");
        }
        __syncthreads();

        const uint32_t sA  = sbase + (kt & 1) * STG_BYTES;
        const uint32_t sAl = sA + 18432, sBh = sA + 36864, sBl = sA + 73728;
#pragma unroll
        for (int kh = 0; kh < 4; kh++) {
            uint32_t a[4][4], bh[2][4], bl[2][4];
            int aoff = (m0 + (lane & 15)) * ROWB + kh * 32 + (lane >> 4) * 16;
            int boff = (n0w + ((lane & 7) | ((lane >> 1) & 8))) * ROWB
                       + kh * 32 + ((lane >> 3) & 1) * 16;
#pragma unroll
            for (int nt = 0; nt < 2; nt++) {
                ldm4(bh[nt], sBh + boff + nt * 16 * ROWB);
                ldm4(bl[nt], sBl + boff + nt * 16 * ROWB);
            }
            // stage 1: a <- Ah; products ah*bh then ah*bl (acc deps 16 apart)
#pragma unroll
            for (int mi = 0; mi < 4; mi++) ldm4(a[mi], sA + aoff + mi * 16 * ROWB);
#pragma unroll
            for (int mi = 0; mi < 4; mi++)
#pragma unroll
                for (int fi = 0; fi < 4; fi++)
                    mma16816(acc[mi][fi], a[mi], &bh[fi >> 1][(fi & 1) * 2]);
#pragma unroll
            for (int mi = 0; mi < 4; mi++)
#pragma unroll
                for (int fi = 0; fi < 4; fi++)
                    mma16816(acc[mi][fi], a[mi], &bl[fi >> 1][(fi & 1) * 2]);
            // stage 2: a <- Al (overwrite, keeps live regs low); product al*bh
#pragma unroll
            for (int mi = 0; mi < 4; mi++) ldm4(a[mi], sAl + aoff + mi * 16 * ROWB);
#pragma unroll
            for (int mi = 0; mi < 4; mi++)
#pragma unroll
                for (int fi = 0; fi < 4; fi++)
                    mma16816(acc[mi][fi], a[mi], &bh[fi >> 1][(fi & 1) * 2]);
        }
        __syncthreads();
    }

    // epilogue
    int tq = lane >> 2, tr = lane & 3;
    if (SCORE) {
        // per-row gelu(acc+bias)·scW reduction; no C store
        float* srow = (float*)smem;
        if (tid < 128) srow[tid] = 0.f;
        __syncthreads();
#pragma unroll
        for (int mi = 0; mi < 4; mi++)
#pragma unroll
            for (int half = 0; half < 2; half++) {
                int rl = m0 + mi * 16 + tq + half * 8;
                float s = 0.f;
#pragma unroll
                for (int fi = 0; fi < 4; fi++) {
                    int col = bn + n0w + fi * 8 + tr * 2;
                    float v0 = geluf(acc[mi][fi][half * 2 + 0] + bias[col]);
                    float v1 = geluf(acc[mi][fi][half * 2 + 1] + bias[col + 1]);
                    s += v0 * scW[col] + v1 * scW[col + 1];
                }
                atomicAdd(&srow[rl], s);
            }
        __syncthreads();
        if (tid < 128) {
            int gr = bm + tid;
            if (gr < M) {
                float t = srow[tid] + scb[0];
                g_tsc[gr] = t;
                atomicMax((unsigned int*)&g_mx, __float_as_uint(fmaxf(t, 0.f)));
            }
        }
        return;
    }
#pragma unroll
    for (int mi = 0; mi < 4; mi++) {
#pragma unroll
        for (int fi = 0; fi < 4; fi++) {
            int col = bn + n0w + fi * 8 + tr * 2;
            float b0 = bias[col], b1 = bias[col + 1];
#pragma unroll
            for (int half = 0; half < 2; half++) {
                int row = bm + m0 + mi * 16 + tq + half * 8;
                if (row >= M) continue;
                float v0 = acc[mi][fi][half * 2 + 0] + b0;
                float v1 = acc[mi][fi][half * 2 + 1] + b1;
                if (ACT) { v0 = geluf(v0); v1 = geluf(v1); }
                if (OUTP) {
                    ushort2 h, l;
                    pack2(v0, h.x, l.x); pack2(v1, h.y, l.y);
                    *(ushort2*)((__nv_bfloat16*)C0 + (size_t)row * ldc + col) = h;
                    *(ushort2*)((__nv_bfloat16*)C1 + (size_t)row * ldc + col) = l;
                } else {
                    *(float2*)((float*)C0 + (size_t)row * ldc + col) = make_float2(v0, v1);
                }
            }
        }
    }
}

// ---------------- init kernels ----------------
__global__ void init_masks_kernel(const float* __restrict__ im) {
    int idx = blockIdx.x * blockDim.x + threadIdx.x;
    if (idx == 0) g_mx = 0.f;
    if (idx >= NTOK) return;
    int b = idx / S2, i = idx % S2;
    auto mask_yes = [&](int j) -> float { return (j <= 1) ? 1.f : im[b * SEQL + (j - 2)]; };
    auto mask_no_end = [&](int j) -> float {
        if (j == 0) return 1.f;
        if (j <= SEQL) return im[b * SEQL + (j - 1)];
        return 0.f;
    };
    float my = mask_yes(i), mne = mask_no_end(i);
    float mask_no_start = (i == 0) ? 0.f : my;
    float last_token = (i < S2 - 1) ? (mask_yes(i + 1) - mask_no_end(i + 1)) : 0.f;
    g_mask[idx] = my;
    g_endm[idx] = my - mne;
    g_selp[idx] = mask_no_start * mne * (1.f - last_token);
    g_active[idx] = my;
    g_ltp[idx] = 0.f;
}

__global__ void init_seqpre_kernel(const float* __restrict__ seqin,
                                   const float* __restrict__ START,
                                   const float* __restrict__ END) {
    int idx = blockIdx.x * blockDim.x + threadIdx.x;
    if (idx >= NTOK * DIM) return;
    int tok = idx / DIM, f = idx % DIM;
    int b = tok / S2, i = tok % S2;
    float base;
    if (i == 0)          base = START[f];
    else if (i <= SEQL)  base = seqin[((size_t)b * SEQL + (i - 1)) * DIM + f];
    else                 base = 0.f;
    float e = g_endm[tok];
    float x = e * END[f] + (1.f - e) * base;
    unsigned short h, l;
    pack2(x, h, l);
    size_t off = (size_t)tok * (2 * DIM) + f;
    g_cc_hi[off] = __ushort_as_bfloat16(h);
    g_cc_lo[off] = __ushort_as_bfloat16(l);
}

__global__ void ln_init_kernel(const float* __restrict__ lng, const float* __restrict__ lnb) {
    int tok = blockIdx.x, f = threadIdx.x;
    float x = g_convOut[(size_t)tok * DIM + f];
    float mean = blockReduceSum256(x) * (1.f / DIM);
    float d = x - mean;
    float r = rsqrtf(blockReduceSum256(d * d) * (1.f / DIM) + 1e-5f);
    g_seq[(size_t)tok * DIM + f] = (d * r * lng[f] + lnb[f]) * g_mask[tok];
}

__global__ void pack_weightT(const float* __restrict__ W, __nv_bfloat16* __restrict__ Hi,
                             __nv_bfloat16* __restrict__ Lo, int K, int N) {
    int i = blockIdx.x * blockDim.x + threadIdx.x;
    if (i >= N * K) return;
    int n = i / K, k = i % K;
    unsigned short h, l;
    pack2(W[(size_t)k * N + n], h, l);
    Hi[i] = __ushort_as_bfloat16(h);
    Lo[i] = __ushort_as_bfloat16(l);
}

// merged pack for w1 + w2
__global__ void pack_w1w2(const float* __restrict__ W1, __nv_bfloat16* __restrict__ H1,
                          __nv_bfloat16* __restrict__ L1,
                          const float* __restrict__ W2, __nv_bfloat16* __restrict__ H2,
                          __nv_bfloat16* __restrict__ L2) {
    int i = blockIdx.x * blockDim.x + threadIdx.x;
    const int n1 = HID * 2 * DIM;
    if (i < n1) {
        int n = i / (2 * DIM), k = i % (2 * DIM);
        unsigned short h, l;
        pack2(W1[(size_t)k * HID + n], h, l);
        H1[i] = __ushort_as_bfloat16(h); L1[i] = __ushort_as_bfloat16(l);
    } else {
        int j = i - n1;
        if (j >= HID * HID) return;
        int n = j / HID, k = j % HID;
        unsigned short h, l;
        pack2(W2[(size_t)k * HID + n], h, l);
        H2[j] = __ushort_as_bfloat16(h); L2[j] = __ushort_as_bfloat16(l);
    }
}

// ---------------- merged scan kernel ----------------
__global__ void scan_kernel(const float* __restrict__ yes_t, const float* __restrict__ no_t) {
    int idx = blockIdx.x * blockDim.x + threadIdx.x;
    if (idx < NB * 64) {
        int b = idx >> 6, f0 = (idx & 63) << 2;
        float4 yf = *(const float4*)(yes_t + f0);
        float4 nf = *(const float4*)(no_t + f0);
        float4 l1 = {0,0,0,0}, l2 = {0,0,0,0}, lc = {0,0,0,0};
        for (int i = 0; i < S2; i++) {
            int tok = b * S2 + i;
            float a = g_active[tok], m = g_mask[tok], lt = g_ltp[tok];
            float w = a * m * m, c = 1.f - a * m + EPSF;
            float4 sv = *(const float4*)(g_seq + (size_t)tok * DIM + f0);
            float4 base;
            base.x = sv.x + lt * yf.x + (1.f - lt) * nf.x;
            base.y = sv.y + lt * yf.y + (1.f - lt) * nf.y;
            base.z = sv.z + lt * yf.z + (1.f - lt) * nf.z;
            base.w = sv.w + lt * yf.w + (1.f - lt) * nf.w;
            size_t fl = (size_t)tok * WD;
            st4p(g_flat_hi + fl + 0 * DIM + f0, g_flat_lo + fl + 0 * DIM + f0, l2);
            st4p(g_flat_hi + fl + 1 * DIM + f0, g_flat_lo + fl + 1 * DIM + f0, l1);
            size_t cp = (size_t)tok * 2 * DIM;
            st4p(g_cc_hi + cp + f0,       g_cc_lo + cp + f0,       lc);
            st4p(g_cc_hi + cp + DIM + f0, g_cc_lo + cp + DIM + f0, sv);
            float4 nl2;
            nl2.x = w * l1.x + c * l2.x; nl2.y = w * l1.y + c * l2.y;
            nl2.z = w * l1.z + c * l2.z; nl2.w = w * l1.w + c * l2.w;
            l1.x = w * base.x + c * l1.x; l1.y = w * base.y + c * l1.y;
            l1.z = w * base.z + c * l1.z; l1.w = w * base.w + c * l1.w;
            lc.x = w * sv.x + c * lc.x; lc.y = w * sv.y + c * lc.y;
            lc.z = w * sv.z + c * lc.z; lc.w = w * sv.w + c * lc.w;
            l2 = nl2;
        }
    } else {
        int j = idx - NB * 64;
        if (j >= NB * 64) return;
        int b = j >> 6, f0 = (j & 63) << 2;
        float4 yf = *(const float4*)(yes_t + f0);
        float4 nf = *(const float4*)(no_t + f0);
        float4 r1 = {0,0,0,0}, r2 = {0,0,0,0};
        for (int i = S2 - 1; i >= 0; i--) {
            int tok = b * S2 + i;
            float a = g_active[tok], m = g_mask[tok], lt = g_ltp[tok];
            float w = a * m * m, c = 1.f - a * m + EPSF;
            float4 sv = *(const float4*)(g_seq + (size_t)tok * DIM + f0);
            float4 base;
            base.x = sv.x + lt * yf.x + (1.f - lt) * nf.x;
            base.y = sv.y + lt * yf.y + (1.f - lt) * nf.y;
            base.z = sv.z + lt * yf.z + (1.f - lt) * nf.z;
            base.w = sv.w + lt * yf.w + (1.f - lt) * nf.w;
            size_t fl = (size_t)tok * WD;
            st4p(g_flat_hi + fl + 2 * DIM + f0, g_flat_lo + fl + 2 * DIM + f0, base);
            st4p(g_flat_hi + fl + 3 * DIM + f0, g_flat_lo + fl + 3 * DIM + f0, r1);
            st4p(g_flat_hi + fl + 4 * DIM + f0, g_flat_lo + fl + 4 * DIM + f0, r2);
            float4 nr2;
            nr2.x = w * r1.x + c * r2.x; nr2.y = w * r1.y + c * r2.y;
            nr2.z = w * r1.z + c * r2.z; nr2.w = w * r1.w + c * r2.w;
            r1.x = w * base.x + c * r1.x; r1.y = w * base.y + c * r1.y;
            r1.z = w * base.z + c * r1.z; r1.w = w * base.w + c * r1.w;
            r2 = nr2;
        }
    }
}

// ---------------- per-step kernels ----------------
__global__ void combine_kernel(const float* __restrict__ lng, const float* __restrict__ lnb) {
    int tok = blockIdx.x, f = threadIdx.x;
    const float* ct = g_contents + (size_t)tok * HID;
    size_t cp = (size_t)tok * 2 * DIM;
    float lc = __bfloat162float(g_cc_hi[cp + f]) + __bfloat162float(g_cc_lo[cp + f]);
    float sv = __bfloat162float(g_cc_hi[cp + DIM + f]) + __bfloat162float(g_cc_lo[cp + DIM + f]);
    float g0 = 1.f / (1.f + expf(-ct[0 * DIM + f]));
    float g1 = 1.f / (1.f + expf(-ct[1 * DIM + f]));
    float g2 = 1.f / (1.f + expf(-ct[2 * DIM + f]));
    float y = g0 * lc + g1 * sv + g2 * ct[3 * DIM + f];
    float mean = blockReduceSum256(y) * (1.f / DIM);
    float d = y - mean;
    float r = rsqrtf(blockReduceSum256(d * d) * (1.f / DIM) + 1e-5f);
    float comp = d * r * lng[f] + lnb[f];
    float mx = g_mx;
    float et = expf(g_tsc[tok] - mx) * g_selp[tok];
    float tp = et / (et + expf(-mx) + EPSF);
    if (f == 0) g_tp[tok] = tp;
    g_seq[(size_t)tok * DIM + f] = (tp * comp + (1.f - tp) * sv) * g_mask[tok];
}

__global__ void deact_kernel() {
    __shared__ float s_a[S2], s_m[S2], s_tp[S2];
    int b = blockIdx.x;
    if (b == 0 && threadIdx.x == 0) g_mx = 0.f;   // reset for next step's score
    for (int i = threadIdx.x; i < S2; i += blockDim.x) {
        int tok = b * S2 + i;
        s_a[i] = g_active[tok]; s_m[i] = g_mask[tok]; s_tp[i] = g_tp[tok];
    }
    __syncthreads();
    if (threadIdx.x == 0) {
        float dacc = 0.f;
        for (int j = S2 - 1; j >= 0; j--) {
            float a = s_a[j], m = s_m[j], tp = s_tp[j];
            float de = a * m * m * dacc;
            s_a[j] = fminf(fmaxf(a * (1.f - de), 0.f), 1.f) * m;
            dacc = tp + (1.f - a * m + EPSF) * dacc;
        }
    }
    __syncthreads();
    for (int i = threadIdx.x; i < S2; i += blockDim.x) {
        int tok = b * S2 + i;
        g_active[tok] = s_a[i];
        g_ltp[tok]    = s_tp[i];
    }
}

__global__ void copy_out_kernel(float* __restrict__ out) {
    int idx = blockIdx.x * blockDim.x + threadIdx.x;
    if (idx < NTOK * DIM) out[idx] = g_seq[idx];
}

// ---------------- launch ----------------
extern "C" void kernel_launch(void* const* d_in, const int* in_sizes, int n_in,
                              void* d_out, int out_size) {
    const float* sequence   = (const float*)d_in[0];
    const float* input_mask = (const float*)d_in[1];
    const float* START = (const float*)d_in[2];
    const float* END   = (const float*)d_in[3];
    const float* yes_t = (const float*)d_in[4];
    const float* no_t  = (const float*)d_in[5];
    const float* convW = (const float*)d_in[6];
    const float* convb = (const float*)d_in[7];
    const float* scW   = (const float*)d_in[8];
    const float* scb   = (const float*)d_in[9];
    const float* itW   = (const float*)d_in[10];
    const float* itb   = (const float*)d_in[11];
    const float* w1W   = (const float*)d_in[12];
    const float* w1b   = (const float*)d_in[13];
    const float* w2W   = (const float*)d_in[14];
    const float* w2b   = (const float*)d_in[15];
    const float* lng   = (const float*)d_in[16];
    const float* lnb   = (const float*)d_in[17];
    float* out = (float*)d_out;

    __nv_bfloat16 *p_flat_hi, *p_flat_lo, *p_cc_hi, *p_cc_lo, *p_inter_hi, *p_inter_lo;
    __nv_bfloat16 *p_convWt_hi, *p_convWt_lo, *p_w1Wt_hi, *p_w1Wt_lo,
                  *p_w2Wt_hi, *p_w2Wt_lo, *p_itWt_hi, *p_itWt_lo;
    float *p_contents, *p_convOut;
    cudaGetSymbolAddress((void**)&p_flat_hi, g_flat_hi);
    cudaGetSymbolAddress((void**)&p_flat_lo, g_flat_lo);
    cudaGetSymbolAddress((void**)&p_cc_hi, g_cc_hi);
    cudaGetSymbolAddress((void**)&p_cc_lo, g_cc_lo);
    cudaGetSymbolAddress((void**)&p_inter_hi, g_inter_hi);
    cudaGetSymbolAddress((void**)&p_inter_lo, g_inter_lo);
    cudaGetSymbolAddress((void**)&p_contents, g_contents);
    cudaGetSymbolAddress((void**)&p_convOut, g_convOut);
    cudaGetSymbolAddress((void**)&p_convWt_hi, g_convWt_hi);
    cudaGetSymbolAddress((void**)&p_convWt_lo, g_convWt_lo);
    cudaGetSymbolAddress((void**)&p_w1Wt_hi, g_w1Wt_hi);
    cudaGetSymbolAddress((void**)&p_w1Wt_lo, g_w1Wt_lo);
    cudaGetSymbolAddress((void**)&p_w2Wt_hi, g_w2Wt_hi);
    cudaGetSymbolAddress((void**)&p_w2Wt_lo, g_w2Wt_lo);
    cudaGetSymbolAddress((void**)&p_itWt_hi, g_itWt_hi);
    cudaGetSymbolAddress((void**)&p_itWt_lo, g_itWt_lo);

    const int SMEMB = 2 * STG_BYTES;   // 221184
    cudaFuncSetAttribute(mma_gemm<0,0,0>, cudaFuncAttributeMaxDynamicSharedMemorySize, SMEMB);
    cudaFuncSetAttribute(mma_gemm<1,1,0>, cudaFuncAttributeMaxDynamicSharedMemorySize, SMEMB);
    cudaFuncSetAttribute(mma_gemm<1,0,1>, cudaFuncAttributeMaxDynamicSharedMemorySize, SMEMB);

    const int THR = 256;
    const int GM = (NTOK + 127) / 128;   // 129

    init_masks_kernel<<<(NTOK + THR - 1) / THR, THR>>>(input_mask);
    init_seqpre_kernel<<<(NTOK * DIM + THR - 1) / THR, THR>>>(sequence, START, END);
    pack_weightT<<<(DIM * DIM + THR - 1) / THR, THR>>>(itW, p_itWt_hi, p_itWt_lo, DIM, DIM);
    pack_weightT<<<(DIM * WD + THR - 1) / THR, THR>>>(convW, p_convWt_hi, p_convWt_lo, WD, DIM);
    pack_w1w2<<<(HID * 2 * DIM + HID * HID + THR - 1) / THR, THR>>>(
        w1W, p_w1Wt_hi, p_w1Wt_lo, w2W, p_w2Wt_hi, p_w2Wt_lo);

    // grid: x = N-tiles (fast-varying, shares A tile), y = M-tiles
    mma_gemm<0,0,0><<<dim3(1, GM), 512, SMEMB>>>(p_cc_hi, p_cc_lo, 2 * DIM,
        p_itWt_hi, p_itWt_lo, itb, p_convOut, nullptr, DIM, NTOK, DIM, nullptr, nullptr);
    ln_init_kernel<<<NTOK, DIM>>>(lng, lnb);

    for (int s = 0; s < NSTEPS; s++) {
        scan_kernel<<<(2 * NB * 64 + THR - 1) / THR, THR>>>(yes_t, no_t);
        mma_gemm<1,0,1><<<dim3(1, GM), 512, SMEMB>>>(p_flat_hi, p_flat_lo, WD,
            p_convWt_hi, p_convWt_lo, convb, nullptr, nullptr, DIM, NTOK, WD, scW, scb);
        mma_gemm<1,1,0><<<dim3(4, GM), 512, SMEMB>>>(p_cc_hi, p_cc_lo, 2 * DIM,
            p_w1Wt_hi, p_w1Wt_lo, w1b, p_inter_hi, p_inter_lo, HID, NTOK, 2 * DIM, nullptr, nullptr);
        mma_gemm<0,0,0><<<dim3(4, GM), 512, SMEMB>>>(p_inter_hi, p_inter_lo, HID,
            p_w2Wt_hi, p_w2Wt_lo, w2b, p_contents, nullptr, HID, NTOK, HID, nullptr, nullptr);
        combine_kernel<<<NTOK, DIM>>>(lng, lnb);
        deact_kernel<<<NB, 128>>>();
    }

    copy_out_kernel<<<(NTOK * DIM + THR - 1) / THR, THR>>>(out);
}

// round 9
// speedup vs baseline: 1.2613x; 1.2613x over previous
#include <cuda_runtime.h>
#include <cuda_fp16.h>
#include <math.h>
#include <stdint.h>

#define NB   32
#define SEQL 512
#define DIM  256
#define S2   514
#define NTOK (NB * S2)
#define HID  1024
#define WD   1280
#define NSTEPS 6
#define EPSF 1e-9f

// planar fp16 hi/lo activation buffers (x = hi + lo, both fp16)
static __device__ __align__(256) __half g_flat_hi[NTOK * WD];
static __device__ __align__(256) __half g_flat_lo[NTOK * WD];
static __device__ __align__(256) __half g_cc_hi[NTOK * 2 * DIM];
static __device__ __align__(256) __half g_cc_lo[NTOK * 2 * DIM];
static __device__ __align__(256) __half g_inter_hi[NTOK * HID];
static __device__ __align__(256) __half g_inter_lo[NTOK * HID];
static __device__ __align__(256) float g_contents[NTOK * HID];
static __device__ __align__(256) float g_convOut[NTOK * DIM];   // init path only
static __device__ __align__(256) float g_seq[NTOK * DIM];
static __device__ float g_tsc[NTOK], g_tp[NTOK], g_ltp[NTOK];
static __device__ float g_active[NTOK], g_mask[NTOK], g_selp[NTOK], g_endm[NTOK];
static __device__ float g_mx;
// pre-transposed weights, single fp16 plane: Wt[n*K+k] = fp16(W[k*N+n])
static __device__ __align__(256) __half g_convWt[DIM * WD];
static __device__ __align__(256) __half g_w1Wt[HID * 2 * DIM];
static __device__ __align__(256) __half g_w2Wt[HID * HID];
static __device__ __align__(256) __half g_itWt[DIM * DIM];

__device__ __forceinline__ float geluf(float x) {
    float x3 = x * x * x;
    return 0.5f * x * (1.f + tanhf(0.7978845608028654f * (x + 0.044715f * x3)));
}
// fp16 hi/lo split: h = fp16(x), l = fp16(x - h); residual ~2^-22 relative
__device__ __forceinline__ void pack2(float x, unsigned short& h, unsigned short& l) {
    __half hh = __float2half_rn(x);
    h = __half_as_ushort(hh);
    l = __half_as_ushort(__float2half_rn(x - __half2float(hh)));
}
__device__ __forceinline__ void st4p(__half* H, __half* L, float4 v) {
    ushort4 h, l;
    pack2(v.x, h.x, l.x); pack2(v.y, h.y, l.y);
    pack2(v.z, h.z, l.z); pack2(v.w, h.w, l.w);
    *(ushort4*)H = h; *(ushort4*)L = l;
}

__device__ __forceinline__ float blockReduceSum256(float v) {
    __shared__ float sh[33];
    int lane = threadIdx.x & 31, wid = threadIdx.x >> 5;
#pragma unroll
    for (int o = 16; o; o >>= 1) v += __shfl_down_sync(0xffffffffu, v, o);
    __syncthreads();
    if (lane == 0) sh[wid] = v;
    __syncthreads();
    if (wid == 0) {
        float t = (lane < 8) ? sh[lane] : 0.f;
#pragma unroll
        for (int o = 16; o; o >>= 1) t += __shfl_down_sync(0xffffffffu, t, o);
        if (lane == 0) sh[32] = t;
    }
    __syncthreads();
    return sh[32];
}

// ---------------- mma.sync helpers ----------------
__device__ __forceinline__ uint32_t s2u(const void* p) { return (uint32_t)__cvta_generic_to_shared(p); }
__device__ __forceinline__ void ldm4(uint32_t* r, uint32_t a) {
    asm volatile("ldmatrix.sync.aligned.m8n8.x4.shared.b16 {%0,%1,%2,%3}, [%4];"
                 : "=r"(r[0]), "=r"(r[1]), "=r"(r[2]), "=r"(r[3]) : "r"(a));
}
__device__ __forceinline__ void mma16816(float* c, const uint32_t* a, const uint32_t* b) {
    asm volatile("mma.sync.aligned.m16n8k16.row.col.f32.f16.f16.f32 "
                 "{%0,%1,%2,%3},{%4,%5,%6,%7},{%8,%9},{%0,%1,%2,%3};"
                 : "+f"(c[0]), "+f"(c[1]), "+f"(c[2]), "+f"(c[3])
                 : "r"(a[0]), "r"(a[1]), "r"(a[2]), "r"(a[3]), "r"(b[0]), "r"(b[1]));
}
__device__ __forceinline__ void cpasync16(uint32_t dst, const void* src, int srcsize) {
    asm volatile("cp.async.cg.shared.global [%0], [%1], 16, %2;"
                 :: "r"(dst), "l"(src), "r"(srcsize) : "memory");
}

// ---------------- GEMM: C[M,N] = (Ah+Al)@B^T + bias (fp16 2-product) ----------------
// CTA 128x256, 512 threads (16 warps of 64x32), K-tile 64, 2-stage cp.async.
// SMEM stage (73728B): Ah[128x144] Al[+18432] B[+36864, 256x144]
// SCORE=1: no C store; epilogue computes tsc[row] = gelu(row)·scW + scb, atomicMax g_mx.
#define STG_BYTES 73728
#define ROWB 144
template <int ACT, int OUTP, int SCORE>
__global__ __launch_bounds__(512, 1) void mma_gemm(
    const __half* __restrict__ Ah, const __half* __restrict__ Al, int lda,
    const __half* __restrict__ B,
    const float* __restrict__ bias, void* __restrict__ C0, void* __restrict__ C1,
    int ldc, int M, int K,
    const float* __restrict__ scW, const float* __restrict__ scb)
{
    extern __shared__ char smem[];
    const uint32_t sbase = s2u(smem);
    const int tid = threadIdx.x, w = tid >> 5, lane = tid & 31;
    const int bm = blockIdx.y * 128, bn = blockIdx.x * 256;
    const int NK = K >> 6;
    const int m0 = (w & 1) * 64, n0w = (w >> 1) * 32;

    float acc[4][4][4];
#pragma unroll
    for (int i = 0; i < 4; i++)
#pragma unroll
        for (int j = 0; j < 4; j++)
#pragma unroll
            for (int e = 0; e < 4; e++) acc[i][j][e] = 0.f;

    auto fill = [&](int st, int kt) {
        int k0 = kt << 6;
#pragma unroll
        for (int q = 0; q < 8; q++) {
            int u = tid + q * 512;               // 4096 units of 16B
            const __half* src;
            uint32_t dst;
            int sz = 16;
            if (u < 2048) {
                int plane = u >> 10, r = (u >> 3) & 127, c = u & 7;
                int gr = bm + r;
                if (gr >= M) { gr = 0; sz = 0; }
                src = (plane ? Al : Ah) + (size_t)gr * lda + k0 + c * 8;
                dst = sbase + st * STG_BYTES + plane * 18432 + r * ROWB + c * 16;
            } else {
                int v = u - 2048;
                int r = (v >> 3) & 255, c = v & 7;
                src = B + (size_t)(bn + r) * K + k0 + c * 8;
                dst = sbase + st * STG_BYTES + 36864 + r * ROWB + c * 16;
            }
            cpasync16(dst, src, sz);
        }
        asm volatile("cp.async.commit_group;" ::: "memory");
    };

    fill(0, 0);
    for (int kt = 0; kt < NK; kt++) {
        if (kt + 1 < NK) {
            fill((kt + 1) & 1, kt + 1);
            asm volatile("cp.async.wait_group 1;" ::: "memory");
        } else {
            asm volatile("cp.async.wait_group 0;" ::: "memory");
        }
        __syncthreads();

        const uint32_t sA  = sbase + (kt & 1) * STG_BYTES;
        const uint32_t sAl = sA + 18432, sB = sA + 36864;
#pragma unroll
        for (int kh = 0; kh < 4; kh++) {
            uint32_t a[4][4], bfr[2][4];
            int aoff = (m0 + (lane & 15)) * ROWB + kh * 32 + (lane >> 4) * 16;
            int boff = (n0w + ((lane & 7) | ((lane >> 1) & 8))) * ROWB
                       + kh * 32 + ((lane >> 3) & 1) * 16;
#pragma unroll
            for (int nt = 0; nt < 2; nt++)
                ldm4(bfr[nt], sB + boff + nt * 16 * ROWB);
            // product 1: ah * b
#pragma unroll
            for (int mi = 0; mi < 4; mi++) ldm4(a[mi], sA + aoff + mi * 16 * ROWB);
#pragma unroll
            for (int mi = 0; mi < 4; mi++)
#pragma unroll
                for (int fi = 0; fi < 4; fi++)
                    mma16816(acc[mi][fi], a[mi], &bfr[fi >> 1][(fi & 1) * 2]);
            // product 2: al * b (overwrite a regs)
#pragma unroll
            for (int mi = 0; mi < 4; mi++) ldm4(a[mi], sAl + aoff + mi * 16 * ROWB);
#pragma unroll
            for (int mi = 0; mi < 4; mi++)
#pragma unroll
                for (int fi = 0; fi < 4; fi++)
                    mma16816(acc[mi][fi], a[mi], &bfr[fi >> 1][(fi & 1) * 2]);
        }
        __syncthreads();
    }

    // epilogue
    int tq = lane >> 2, tr = lane & 3;
    if (SCORE) {
        float* srow = (float*)smem;
        if (tid < 128) srow[tid] = 0.f;
        __syncthreads();
#pragma unroll
        for (int mi = 0; mi < 4; mi++)
#pragma unroll
            for (int half = 0; half < 2; half++) {
                int rl = m0 + mi * 16 + tq + half * 8;
                float s = 0.f;
#pragma unroll
                for (int fi = 0; fi < 4; fi++) {
                    int col = bn + n0w + fi * 8 + tr * 2;
                    float v0 = geluf(acc[mi][fi][half * 2 + 0] + bias[col]);
                    float v1 = geluf(acc[mi][fi][half * 2 + 1] + bias[col + 1]);
                    s += v0 * scW[col] + v1 * scW[col + 1];
                }
                atomicAdd(&srow[rl], s);
            }
        __syncthreads();
        if (tid < 128) {
            int gr = bm + tid;
            if (gr < M) {
                float t = srow[tid] + scb[0];
                g_tsc[gr] = t;
                atomicMax((unsigned int*)&g_mx, __float_as_uint(fmaxf(t, 0.f)));
            }
        }
        return;
    }
#pragma unroll
    for (int mi = 0; mi < 4; mi++) {
#pragma unroll
        for (int fi = 0; fi < 4; fi++) {
            int col = bn + n0w + fi * 8 + tr * 2;
            float b0 = bias[col], b1 = bias[col + 1];
#pragma unroll
            for (int half = 0; half < 2; half++) {
                int row = bm + m0 + mi * 16 + tq + half * 8;
                if (row >= M) continue;
                float v0 = acc[mi][fi][half * 2 + 0] + b0;
                float v1 = acc[mi][fi][half * 2 + 1] + b1;
                if (ACT) { v0 = geluf(v0); v1 = geluf(v1); }
                if (OUTP) {
                    ushort2 h, l;
                    pack2(v0, h.x, l.x); pack2(v1, h.y, l.y);
                    *(ushort2*)((__half*)C0 + (size_t)row * ldc + col) = h;
                    *(ushort2*)((__half*)C1 + (size_t)row * ldc + col) = l;
                } else {
                    *(float2*)((float*)C0 + (size_t)row * ldc + col) = make_float2(v0, v1);
                }
            }
        }
    }
}

// ---------------- init kernels ----------------
__global__ void init_masks_kernel(const float* __restrict__ im) {
    int idx = blockIdx.x * blockDim.x + threadIdx.x;
    if (idx == 0) g_mx = 0.f;
    if (idx >= NTOK) return;
    int b = idx / S2, i = idx % S2;
    auto mask_yes = [&](int j) -> float { return (j <= 1) ? 1.f : im[b * SEQL + (j - 2)]; };
    auto mask_no_end = [&](int j) -> float {
        if (j == 0) return 1.f;
        if (j <= SEQL) return im[b * SEQL + (j - 1)];
        return 0.f;
    };
    float my = mask_yes(i), mne = mask_no_end(i);
    float mask_no_start = (i == 0) ? 0.f : my;
    float last_token = (i < S2 - 1) ? (mask_yes(i + 1) - mask_no_end(i + 1)) : 0.f;
    g_mask[idx] = my;
    g_endm[idx] = my - mne;
    g_selp[idx] = mask_no_start * mne * (1.f - last_token);
    g_active[idx] = my;
    g_ltp[idx] = 0.f;
}

__global__ void init_seqpre_kernel(const float* __restrict__ seqin,
                                   const float* __restrict__ START,
                                   const float* __restrict__ END) {
    int idx = blockIdx.x * blockDim.x + threadIdx.x;
    if (idx >= NTOK * DIM) return;
    int tok = idx / DIM, f = idx % DIM;
    int b = tok / S2, i = tok % S2;
    float base;
    if (i == 0)          base = START[f];
    else if (i <= SEQL)  base = seqin[((size_t)b * SEQL + (i - 1)) * DIM + f];
    else                 base = 0.f;
    float e = g_endm[tok];
    float x = e * END[f] + (1.f - e) * base;
    unsigned short h, l;
    pack2(x, h, l);
    size_t off = (size_t)tok * (2 * DIM) + f;
    g_cc_hi[off] = __ushort_as_half(h);
    g_cc_lo[off] = __ushort_as_half(l);
}

__global__ void ln_init_kernel(const float* __restrict__ lng, const float* __restrict__ lnb) {
    int tok = blockIdx.x, f = threadIdx.x;
    float x = g_convOut[(size_t)tok * DIM + f];
    float mean = blockReduceSum256(x) * (1.f / DIM);
    float d = x - mean;
    float r = rsqrtf(blockReduceSum256(d * d) * (1.f / DIM) + 1e-5f);
    g_seq[(size_t)tok * DIM + f] = (d * r * lng[f] + lnb[f]) * g_mask[tok];
}

__global__ void pack_weightT(const float* __restrict__ W, __half* __restrict__ Wt,
                             int K, int N) {
    int i = blockIdx.x * blockDim.x + threadIdx.x;
    if (i >= N * K) return;
    int n = i / K, k = i % K;
    Wt[i] = __float2half_rn(W[(size_t)k * N + n]);
}

__global__ void pack_w1w2(const float* __restrict__ W1, __half* __restrict__ T1,
                          const float* __restrict__ W2, __half* __restrict__ T2) {
    int i = blockIdx.x * blockDim.x + threadIdx.x;
    const int n1 = HID * 2 * DIM;
    if (i < n1) {
        int n = i / (2 * DIM), k = i % (2 * DIM);
        T1[i] = __float2half_rn(W1[(size_t)k * HID + n]);
    } else {
        int j = i - n1;
        if (j >= HID * HID) return;
        int n = j / HID, k = j % HID;
        T2[j] = __float2half_rn(W2[(size_t)k * HID + n]);
    }
}

// ---------------- merged scan kernel ----------------
__global__ void scan_kernel(const float* __restrict__ yes_t, const float* __restrict__ no_t) {
    int idx = blockIdx.x * blockDim.x + threadIdx.x;
    if (idx < NB * 64) {
        int b = idx >> 6, f0 = (idx & 63) << 2;
        float4 yf = *(const float4*)(yes_t + f0);
        float4 nf = *(const float4*)(no_t + f0);
        float4 l1 = {0,0,0,0}, l2 = {0,0,0,0}, lc = {0,0,0,0};
        for (int i = 0; i < S2; i++) {
            int tok = b * S2 + i;
            float a = g_active[tok], m = g_mask[tok], lt = g_ltp[tok];
            float w = a * m * m, c = 1.f - a * m + EPSF;
            float4 sv = *(const float4*)(g_seq + (size_t)tok * DIM + f0);
            float4 base;
            base.x = sv.x + lt * yf.x + (1.f - lt) * nf.x;
            base.y = sv.y + lt * yf.y + (1.f - lt) * nf.y;
            base.z = sv.z + lt * yf.z + (1.f - lt) * nf.z;
            base.w = sv.w + lt * yf.w + (1.f - lt) * nf.w;
            size_t fl = (size_t)tok * WD;
            st4p(g_flat_hi + fl + 0 * DIM + f0, g_flat_lo + fl + 0 * DIM + f0, l2);
            st4p(g_flat_hi + fl + 1 * DIM + f0, g_flat_lo + fl + 1 * DIM + f0, l1);
            size_t cp = (size_t)tok * 2 * DIM;
            st4p(g_cc_hi + cp + f0,       g_cc_lo + cp + f0,       lc);
            st4p(g_cc_hi + cp + DIM + f0, g_cc_lo + cp + DIM + f0, sv);
            float4 nl2;
            nl2.x = w * l1.x + c * l2.x; nl2.y = w * l1.y + c * l2.y;
            nl2.z = w * l1.z + c * l2.z; nl2.w = w * l1.w + c * l2.w;
            l1.x = w * base.x + c * l1.x; l1.y = w * base.y + c * l1.y;
            l1.z = w * base.z + c * l1.z; l1.w = w * base.w + c * l1.w;
            lc.x = w * sv.x + c * lc.x; lc.y = w * sv.y + c * lc.y;
            lc.z = w * sv.z + c * lc.z; lc.w = w * sv.w + c * lc.w;
            l2 = nl2;
        }
    } else {
        int j = idx - NB * 64;
        if (j >= NB * 64) return;
        int b = j >> 6, f0 = (j & 63) << 2;
        float4 yf = *(const float4*)(yes_t + f0);
        float4 nf = *(const float4*)(no_t + f0);
        float4 r1 = {0,0,0,0}, r2 = {0,0,0,0};
        for (int i = S2 - 1; i >= 0; i--) {
            int tok = b * S2 + i;
            float a = g_active[tok], m = g_mask[tok], lt = g_ltp[tok];
            float w = a * m * m, c = 1.f - a * m + EPSF;
            float4 sv = *(const float4*)(g_seq + (size_t)tok * DIM + f0);
            float4 base;
            base.x = sv.x + lt * yf.x + (1.f - lt) * nf.x;
            base.y = sv.y + lt * yf.y + (1.f - lt) * nf.y;
            base.z = sv.z + lt * yf.z + (1.f - lt) * nf.z;
            base.w = sv.w + lt * yf.w + (1.f - lt) * nf.w;
            size_t fl = (size_t)tok * WD;
            st4p(g_flat_hi + fl + 2 * DIM + f0, g_flat_lo + fl + 2 * DIM + f0, base);
            st4p(g_flat_hi + fl + 3 * DIM + f0, g_flat_lo + fl + 3 * DIM + f0, r1);
            st4p(g_flat_hi + fl + 4 * DIM + f0, g_flat_lo + fl + 4 * DIM + f0, r2);
            float4 nr2;
            nr2.x = w * r1.x + c * r2.x; nr2.y = w * r1.y + c * r2.y;
            nr2.z = w * r1.z + c * r2.z; nr2.w = w * r1.w + c * r2.w;
            r1.x = w * base.x + c * r1.x; r1.y = w * base.y + c * r1.y;
            r1.z = w * base.z + c * r1.z; r1.w = w * base.w + c * r1.w;
            r2 = nr2;
        }
    }
}

// ---------------- per-step kernels ----------------
__global__ void combine_kernel(const float* __restrict__ lng, const float* __restrict__ lnb) {
    int tok = blockIdx.x, f = threadIdx.x;
    const float* ct = g_contents + (size_t)tok * HID;
    size_t cp = (size_t)tok * 2 * DIM;
    float lc = __half2float(g_cc_hi[cp + f]) + __half2float(g_cc_lo[cp + f]);
    float sv = __half2float(g_cc_hi[cp + DIM + f]) + __half2float(g_cc_lo[cp + DIM + f]);
    float g0 = 1.f / (1.f + expf(-ct[0 * DIM + f]));
    float g1 = 1.f / (1.f + expf(-ct[1 * DIM + f]));
    float g2 = 1.f / (1.f + expf(-ct[2 * DIM + f]));
    float y = g0 * lc + g1 * sv + g2 * ct[3 * DIM + f];
    float mean = blockReduceSum256(y) * (1.f / DIM);
    float d = y - mean;
    float r = rsqrtf(blockReduceSum256(d * d) * (1.f / DIM) + 1e-5f);
    float comp = d * r * lng[f] + lnb[f];
    float mx = g_mx;
    float et = expf(g_tsc[tok] - mx) * g_selp[tok];
    float tp = et / (et + expf(-mx) + EPSF);
    if (f == 0) g_tp[tok] = tp;
    g_seq[(size_t)tok * DIM + f] = (tp * comp + (1.f - tp) * sv) * g_mask[tok];
}

__global__ void deact_kernel() {
    __shared__ float s_a[S2], s_m[S2], s_tp[S2];
    int b = blockIdx.x;
    if (b == 0 && threadIdx.x == 0) g_mx = 0.f;   // reset for next step's score
    for (int i = threadIdx.x; i < S2; i += blockDim.x) {
        int tok = b * S2 + i;
        s_a[i] = g_active[tok]; s_m[i] = g_mask[tok]; s_tp[i] = g_tp[tok];
    }
    __syncthreads();
    if (threadIdx.x == 0) {
        float dacc = 0.f;
        for (int j = S2 - 1; j >= 0; j--) {
            float a = s_a[j], m = s_m[j], tp = s_tp[j];
            float de = a * m * m * dacc;
            s_a[j] = fminf(fmaxf(a * (1.f - de), 0.f), 1.f) * m;
            dacc = tp + (1.f - a * m + EPSF) * dacc;
        }
    }
    __syncthreads();
    for (int i = threadIdx.x; i < S2; i += blockDim.x) {
        int tok = b * S2 + i;
        g_active[tok] = s_a[i];
        g_ltp[tok]    = s_tp[i];
    }
}

__global__ void copy_out_kernel(float* __restrict__ out) {
    int idx = blockIdx.x * blockDim.x + threadIdx.x;
    if (idx < NTOK * DIM) out[idx] = g_seq[idx];
}

// ---------------- launch ----------------
extern "C" void kernel_launch(void* const* d_in, const int* in_sizes, int n_in,
                              void* d_out, int out_size) {
    const float* sequence   = (const float*)d_in[0];
    const float* input_mask = (const float*)d_in[1];
    const float* START = (const float*)d_in[2];
    const float* END   = (const float*)d_in[3];
    const float* yes_t = (const float*)d_in[4];
    const float* no_t  = (const float*)d_in[5];
    const float* convW = (const float*)d_in[6];
    const float* convb = (const float*)d_in[7];
    const float* scW   = (const float*)d_in[8];
    const float* scb   = (const float*)d_in[9];
    const float* itW   = (const float*)d_in[10];
    const float* itb   = (const float*)d_in[11];
    const float* w1W   = (const float*)d_in[12];
    const float* w1b   = (const float*)d_in[13];
    const float* w2W   = (const float*)d_in[14];
    const float* w2b   = (const float*)d_in[15];
    const float* lng   = (const float*)d_in[16];
    const float* lnb   = (const float*)d_in[17];
    float* out = (float*)d_out;

    __half *p_flat_hi, *p_flat_lo, *p_cc_hi, *p_cc_lo, *p_inter_hi, *p_inter_lo;
    __half *p_convWt, *p_w1Wt, *p_w2Wt, *p_itWt;
    float *p_contents, *p_convOut;
    cudaGetSymbolAddress((void**)&p_flat_hi, g_flat_hi);
    cudaGetSymbolAddress((void**)&p_flat_lo, g_flat_lo);
    cudaGetSymbolAddress((void**)&p_cc_hi, g_cc_hi);
    cudaGetSymbolAddress((void**)&p_cc_lo, g_cc_lo);
    cudaGetSymbolAddress((void**)&p_inter_hi, g_inter_hi);
    cudaGetSymbolAddress((void**)&p_inter_lo, g_inter_lo);
    cudaGetSymbolAddress((void**)&p_contents, g_contents);
    cudaGetSymbolAddress((void**)&p_convOut, g_convOut);
    cudaGetSymbolAddress((void**)&p_convWt, g_convWt);
    cudaGetSymbolAddress((void**)&p_w1Wt, g_w1Wt);
    cudaGetSymbolAddress((void**)&p_w2Wt, g_w2Wt);
    cudaGetSymbolAddress((void**)&p_itWt, g_itWt);

    const int SMEMB = 2 * STG_BYTES;   // 147456
    cudaFuncSetAttribute(mma_gemm<0,0,0>, cudaFuncAttributeMaxDynamicSharedMemorySize, SMEMB);
    cudaFuncSetAttribute(mma_gemm<1,1,0>, cudaFuncAttributeMaxDynamicSharedMemorySize, SMEMB);
    cudaFuncSetAttribute(mma_gemm<1,0,1>, cudaFuncAttributeMaxDynamicSharedMemorySize, SMEMB);

    const int THR = 256;
    const int GM = (NTOK + 127) / 128;   // 129

    init_masks_kernel<<<(NTOK + THR - 1) / THR, THR>>>(input_mask);
    init_seqpre_kernel<<<(NTOK * DIM + THR - 1) / THR, THR>>>(sequence, START, END);
    pack_weightT<<<(DIM * DIM + THR - 1) / THR, THR>>>(itW, p_itWt, DIM, DIM);
    pack_weightT<<<(DIM * WD + THR - 1) / THR, THR>>>(convW, p_convWt, WD, DIM);
    pack_w1w2<<<(HID * 2 * DIM + HID * HID + THR - 1) / THR, THR>>>(
        w1W, p_w1Wt, w2W, p_w2Wt);

    // grid: x = N-tiles (fast-varying, shares A tile), y = M-tiles
    mma_gemm<0,0,0><<<dim3(1, GM), 512, SMEMB>>>(p_cc_hi, p_cc_lo, 2 * DIM,
        p_itWt, itb, p_convOut, nullptr, DIM, NTOK, DIM, nullptr, nullptr);
    ln_init_kernel<<<NTOK, DIM>>>(lng, lnb);

    for (int s = 0; s < NSTEPS; s++) {
        scan_kernel<<<(2 * NB * 64 + THR - 1) / THR, THR>>>(yes_t, no_t);
        mma_gemm<1,0,1><<<dim3(1, GM), 512, SMEMB>>>(p_flat_hi, p_flat_lo, WD,
            p_convWt, convb, nullptr, nullptr, DIM, NTOK, WD, scW, scb);
        mma_gemm<1,1,0><<<dim3(4, GM), 512, SMEMB>>>(p_cc_hi, p_cc_lo, 2 * DIM,
            p_w1Wt, w1b, p_inter_hi, p_inter_lo, HID, NTOK, 2 * DIM, nullptr, nullptr);
        mma_gemm<0,0,0><<<dim3(4, GM), 512, SMEMB>>>(p_inter_hi, p_inter_lo, HID,
            p_w2Wt, w2b, p_contents, nullptr, HID, NTOK, HID, nullptr, nullptr);
        combine_kernel<<<NTOK, DIM>>>(lng, lnb);
        deact_kernel<<<NB, 128>>>();
    }

    copy_out_kernel<<<(NTOK * DIM + THR - 1) / THR, THR>>>(out);
}

// round 10
// speedup vs baseline: 1.8191x; 1.4423x over previous
#include <cuda_runtime.h>
#include <cuda_fp16.h>
#include <math.h>
#include <stdint.h>

#define NB   32
#define SEQL 512
#define DIM  256
#define S2   514
#define NTOK (NB * S2)
#define HID  1024
#define WD   1280
#define NSTEPS 6
#define EPSF 1e-9f

// single-plane fp16 activation buffers (GEMM operands)
static __device__ __align__(256) __half g_flat[NTOK * WD];
static __device__ __align__(256) __half g_cc[NTOK * 2 * DIM];
static __device__ __align__(256) __half g_inter[NTOK * HID];
static __device__ __align__(256) float g_contents[NTOK * HID];
static __device__ __align__(256) float g_convOut[NTOK * DIM];   // init path only
static __device__ __align__(256) float g_seq[NTOK * DIM];       // fp32 state (exact blend path)
static __device__ float g_tsc[NTOK], g_tp[NTOK], g_ltp[NTOK];
static __device__ float g_active[NTOK], g_mask[NTOK], g_selp[NTOK], g_endm[NTOK];
static __device__ float g_mx;
// pre-transposed fp16 weights: Wt[n*K+k] = fp16(W[k*N+n])
static __device__ __align__(256) __half g_convWt[DIM * WD];
static __device__ __align__(256) __half g_w1Wt[HID * 2 * DIM];
static __device__ __align__(256) __half g_w2Wt[HID * HID];
static __device__ __align__(256) __half g_itWt[DIM * DIM];

__device__ __forceinline__ float geluf(float x) {
    float x3 = x * x * x;
    return 0.5f * x * (1.f + tanhf(0.7978845608028654f * (x + 0.044715f * x3)));
}
__device__ __forceinline__ void st4h(__half* H, float4 v) {
    ushort4 h;
    h.x = __half_as_ushort(__float2half_rn(v.x));
    h.y = __half_as_ushort(__float2half_rn(v.y));
    h.z = __half_as_ushort(__float2half_rn(v.z));
    h.w = __half_as_ushort(__float2half_rn(v.w));
    *(ushort4*)H = h;
}

__device__ __forceinline__ float blockReduceSum256(float v) {
    __shared__ float sh[33];
    int lane = threadIdx.x & 31, wid = threadIdx.x >> 5;
#pragma unroll
    for (int o = 16; o; o >>= 1) v += __shfl_down_sync(0xffffffffu, v, o);
    __syncthreads();
    if (lane == 0) sh[wid] = v;
    __syncthreads();
    if (wid == 0) {
        float t = (lane < 8) ? sh[lane] : 0.f;
#pragma unroll
        for (int o = 16; o; o >>= 1) t += __shfl_down_sync(0xffffffffu, t, o);
        if (lane == 0) sh[32] = t;
    }
    __syncthreads();
    return sh[32];
}

// ---------------- mma.sync helpers ----------------
__device__ __forceinline__ uint32_t s2u(const void* p) { return (uint32_t)__cvta_generic_to_shared(p); }
__device__ __forceinline__ void ldm4(uint32_t* r, uint32_t a) {
    asm volatile("ldmatrix.sync.aligned.m8n8.x4.shared.b16 {%0,%1,%2,%3}, [%4];"
                 : "=r"(r[0]), "=r"(r[1]), "=r"(r[2]), "=r"(r[3]) : "r"(a));
}
__device__ __forceinline__ void mma16816(float* c, const uint32_t* a, const uint32_t* b) {
    asm volatile("mma.sync.aligned.m16n8k16.row.col.f32.f16.f16.f32 "
                 "{%0,%1,%2,%3},{%4,%5,%6,%7},{%8,%9},{%0,%1,%2,%3};"
                 : "+f"(c[0]), "+f"(c[1]), "+f"(c[2]), "+f"(c[3])
                 : "r"(a[0]), "r"(a[1]), "r"(a[2]), "r"(a[3]), "r"(b[0]), "r"(b[1]));
}
__device__ __forceinline__ void cpasync16(uint32_t dst, const void* src, int srcsize) {
    asm volatile("cp.async.cg.shared.global [%0], [%1], 16, %2;"
                 :: "r"(dst), "l"(src), "r"(srcsize) : "memory");
}

// ---------------- GEMM: C[M,N] = A@B^T + bias (plain fp16) ----------------
// CTA 128x256, 512 threads (16 warps of 64x32), K-tile 64, 2-stage cp.async.
// SMEM stage (55296B): A[128x144] B[+18432, 256x144]
// SCORE=1: no C store; epilogue computes tsc[row] = gelu(row)·scW + scb, atomicMax g_mx.
#define STG_BYTES 55296
#define ROWB 144
template <int ACT, int OUTP, int SCORE>
__global__ __launch_bounds__(512, 1) void mma_gemm(
    const __half* __restrict__ A, int lda,
    const __half* __restrict__ B,
    const float* __restrict__ bias, void* __restrict__ C0,
    int ldc, int M, int K,
    const float* __restrict__ scW, const float* __restrict__ scb)
{
    extern __shared__ char smem[];
    const uint32_t sbase = s2u(smem);
    const int tid = threadIdx.x, w = tid >> 5, lane = tid & 31;
    const int bm = blockIdx.y * 128, bn = blockIdx.x * 256;
    const int NK = K >> 6;
    const int m0 = (w & 1) * 64, n0w = (w >> 1) * 32;

    float acc[4][4][4];
#pragma unroll
    for (int i = 0; i < 4; i++)
#pragma unroll
        for (int j = 0; j < 4; j++)
#pragma unroll
            for (int e = 0; e < 4; e++) acc[i][j][e] = 0.f;

    auto fill = [&](int st, int kt) {
        int k0 = kt << 6;
#pragma unroll
        for (int q = 0; q < 6; q++) {
            int u = tid + q * 512;               // 3072 units of 16B
            const __half* src;
            uint32_t dst;
            int sz = 16;
            if (u < 1024) {
                int r = u >> 3, c = u & 7;
                int gr = bm + r;
                if (gr >= M) { gr = 0; sz = 0; }
                src = A + (size_t)gr * lda + k0 + c * 8;
                dst = sbase + st * STG_BYTES + r * ROWB + c * 16;
            } else {
                int v = u - 1024;
                int r = (v >> 3) & 255, c = v & 7;
                src = B + (size_t)(bn + r) * K + k0 + c * 8;
                dst = sbase + st * STG_BYTES + 18432 + r * ROWB + c * 16;
            }
            cpasync16(dst, src, sz);
        }
        asm volatile("cp.async.commit_group;" ::: "memory");
    };

    fill(0, 0);
    for (int kt = 0; kt < NK; kt++) {
        if (kt + 1 < NK) {
            fill((kt + 1) & 1, kt + 1);
            asm volatile("cp.async.wait_group 1;" ::: "memory");
        } else {
            asm volatile("cp.async.wait_group 0;" ::: "memory");
        }
        __syncthreads();

        const uint32_t sA = sbase + (kt & 1) * STG_BYTES;
        const uint32_t sB = sA + 18432;
#pragma unroll
        for (int kh = 0; kh < 4; kh++) {
            uint32_t a[4][4], bfr[2][4];
            int aoff = (m0 + (lane & 15)) * ROWB + kh * 32 + (lane >> 4) * 16;
            int boff = (n0w + ((lane & 7) | ((lane >> 1) & 8))) * ROWB
                       + kh * 32 + ((lane >> 3) & 1) * 16;
#pragma unroll
            for (int nt = 0; nt < 2; nt++)
                ldm4(bfr[nt], sB + boff + nt * 16 * ROWB);
#pragma unroll
            for (int mi = 0; mi < 4; mi++) ldm4(a[mi], sA + aoff + mi * 16 * ROWB);
#pragma unroll
            for (int mi = 0; mi < 4; mi++)
#pragma unroll
                for (int fi = 0; fi < 4; fi++)
                    mma16816(acc[mi][fi], a[mi], &bfr[fi >> 1][(fi & 1) * 2]);
        }
        __syncthreads();
    }

    // epilogue
    int tq = lane >> 2, tr = lane & 3;
    if (SCORE) {
        float* srow = (float*)smem;
        if (tid < 128) srow[tid] = 0.f;
        __syncthreads();
#pragma unroll
        for (int mi = 0; mi < 4; mi++)
#pragma unroll
            for (int half = 0; half < 2; half++) {
                int rl = m0 + mi * 16 + tq + half * 8;
                float s = 0.f;
#pragma unroll
                for (int fi = 0; fi < 4; fi++) {
                    int col = bn + n0w + fi * 8 + tr * 2;
                    float v0 = geluf(acc[mi][fi][half * 2 + 0] + bias[col]);
                    float v1 = geluf(acc[mi][fi][half * 2 + 1] + bias[col + 1]);
                    s += v0 * scW[col] + v1 * scW[col + 1];
                }
                atomicAdd(&srow[rl], s);
            }
        __syncthreads();
        if (tid < 128) {
            int gr = bm + tid;
            if (gr < M) {
                float t = srow[tid] + scb[0];
                g_tsc[gr] = t;
                atomicMax((unsigned int*)&g_mx, __float_as_uint(fmaxf(t, 0.f)));
            }
        }
        return;
    }
#pragma unroll
    for (int mi = 0; mi < 4; mi++) {
#pragma unroll
        for (int fi = 0; fi < 4; fi++) {
            int col = bn + n0w + fi * 8 + tr * 2;
            float b0 = bias[col], b1 = bias[col + 1];
#pragma unroll
            for (int half = 0; half < 2; half++) {
                int row = bm + m0 + mi * 16 + tq + half * 8;
                if (row >= M) continue;
                float v0 = acc[mi][fi][half * 2 + 0] + b0;
                float v1 = acc[mi][fi][half * 2 + 1] + b1;
                if (ACT) { v0 = geluf(v0); v1 = geluf(v1); }
                if (OUTP) {
                    ushort2 h;
                    h.x = __half_as_ushort(__float2half_rn(v0));
                    h.y = __half_as_ushort(__float2half_rn(v1));
                    *(ushort2*)((__half*)C0 + (size_t)row * ldc + col) = h;
                } else {
                    *(float2*)((float*)C0 + (size_t)row * ldc + col) = make_float2(v0, v1);
                }
            }
        }
    }
}

// ---------------- init kernels ----------------
__global__ void init_masks_kernel(const float* __restrict__ im) {
    int idx = blockIdx.x * blockDim.x + threadIdx.x;
    if (idx == 0) g_mx = 0.f;
    if (idx >= NTOK) return;
    int b = idx / S2, i = idx % S2;
    auto mask_yes = [&](int j) -> float { return (j <= 1) ? 1.f : im[b * SEQL + (j - 2)]; };
    auto mask_no_end = [&](int j) -> float {
        if (j == 0) return 1.f;
        if (j <= SEQL) return im[b * SEQL + (j - 1)];
        return 0.f;
    };
    float my = mask_yes(i), mne = mask_no_end(i);
    float mask_no_start = (i == 0) ? 0.f : my;
    float last_token = (i < S2 - 1) ? (mask_yes(i + 1) - mask_no_end(i + 1)) : 0.f;
    g_mask[idx] = my;
    g_endm[idx] = my - mne;
    g_selp[idx] = mask_no_start * mne * (1.f - last_token);
    g_active[idx] = my;
    g_ltp[idx] = 0.f;
}

__global__ void init_seqpre_kernel(const float* __restrict__ seqin,
                                   const float* __restrict__ START,
                                   const float* __restrict__ END) {
    int idx = blockIdx.x * blockDim.x + threadIdx.x;
    if (idx >= NTOK * DIM) return;
    int tok = idx / DIM, f = idx % DIM;
    int b = tok / S2, i = tok % S2;
    float base;
    if (i == 0)          base = START[f];
    else if (i <= SEQL)  base = seqin[((size_t)b * SEQL + (i - 1)) * DIM + f];
    else                 base = 0.f;
    float e = g_endm[tok];
    float x = e * END[f] + (1.f - e) * base;
    g_cc[(size_t)tok * (2 * DIM) + f] = __float2half_rn(x);
}

__global__ void ln_init_kernel(const float* __restrict__ lng, const float* __restrict__ lnb) {
    int tok = blockIdx.x, f = threadIdx.x;
    float x = g_convOut[(size_t)tok * DIM + f];
    float mean = blockReduceSum256(x) * (1.f / DIM);
    float d = x - mean;
    float r = rsqrtf(blockReduceSum256(d * d) * (1.f / DIM) + 1e-5f);
    g_seq[(size_t)tok * DIM + f] = (d * r * lng[f] + lnb[f]) * g_mask[tok];
}

__global__ void pack_weightT(const float* __restrict__ W, __half* __restrict__ Wt,
                             int K, int N) {
    int i = blockIdx.x * blockDim.x + threadIdx.x;
    if (i >= N * K) return;
    int n = i / K, k = i % K;
    Wt[i] = __float2half_rn(W[(size_t)k * N + n]);
}

__global__ void pack_w1w2(const float* __restrict__ W1, __half* __restrict__ T1,
                          const float* __restrict__ W2, __half* __restrict__ T2) {
    int i = blockIdx.x * blockDim.x + threadIdx.x;
    const int n1 = HID * 2 * DIM;
    if (i < n1) {
        int n = i / (2 * DIM), k = i % (2 * DIM);
        T1[i] = __float2half_rn(W1[(size_t)k * HID + n]);
    } else {
        int j = i - n1;
        if (j >= HID * HID) return;
        int n = j / HID, k = j % HID;
        T2[j] = __float2half_rn(W2[(size_t)k * HID + n]);
    }
}

// ---------------- merged scan kernel ----------------
__global__ void scan_kernel(const float* __restrict__ yes_t, const float* __restrict__ no_t) {
    int idx = blockIdx.x * blockDim.x + threadIdx.x;
    if (idx < NB * 64) {
        int b = idx >> 6, f0 = (idx & 63) << 2;
        float4 yf = *(const float4*)(yes_t + f0);
        float4 nf = *(const float4*)(no_t + f0);
        float4 l1 = {0,0,0,0}, l2 = {0,0,0,0}, lc = {0,0,0,0};
        for (int i = 0; i < S2; i++) {
            int tok = b * S2 + i;
            float a = g_active[tok], m = g_mask[tok], lt = g_ltp[tok];
            float w = a * m * m, c = 1.f - a * m + EPSF;
            float4 sv = *(const float4*)(g_seq + (size_t)tok * DIM + f0);
            float4 base;
            base.x = sv.x + lt * yf.x + (1.f - lt) * nf.x;
            base.y = sv.y + lt * yf.y + (1.f - lt) * nf.y;
            base.z = sv.z + lt * yf.z + (1.f - lt) * nf.z;
            base.w = sv.w + lt * yf.w + (1.f - lt) * nf.w;
            size_t fl = (size_t)tok * WD;
            st4h(g_flat + fl + 0 * DIM + f0, l2);
            st4h(g_flat + fl + 1 * DIM + f0, l1);
            size_t cp = (size_t)tok * 2 * DIM;
            st4h(g_cc + cp + f0,       lc);
            st4h(g_cc + cp + DIM + f0, sv);
            float4 nl2;
            nl2.x = w * l1.x + c * l2.x; nl2.y = w * l1.y + c * l2.y;
            nl2.z = w * l1.z + c * l2.z; nl2.w = w * l1.w + c * l2.w;
            l1.x = w * base.x + c * l1.x; l1.y = w * base.y + c * l1.y;
            l1.z = w * base.z + c * l1.z; l1.w = w * base.w + c * l1.w;
            lc.x = w * sv.x + c * lc.x; lc.y = w * sv.y + c * lc.y;
            lc.z = w * sv.z + c * lc.z; lc.w = w * sv.w + c * lc.w;
            l2 = nl2;
        }
    } else {
        int j = idx - NB * 64;
        if (j >= NB * 64) return;
        int b = j >> 6, f0 = (j & 63) << 2;
        float4 yf = *(const float4*)(yes_t + f0);
        float4 nf = *(const float4*)(no_t + f0);
        float4 r1 = {0,0,0,0}, r2 = {0,0,0,0};
        for (int i = S2 - 1; i >= 0; i--) {
            int tok = b * S2 + i;
            float a = g_active[tok], m = g_mask[tok], lt = g_ltp[tok];
            float w = a * m * m, c = 1.f - a * m + EPSF;
            float4 sv = *(const float4*)(g_seq + (size_t)tok * DIM + f0);
            float4 base;
            base.x = sv.x + lt * yf.x + (1.f - lt) * nf.x;
            base.y = sv.y + lt * yf.y + (1.f - lt) * nf.y;
            base.z = sv.z + lt * yf.z + (1.f - lt) * nf.z;
            base.w = sv.w + lt * yf.w + (1.f - lt) * nf.w;
            size_t fl = (size_t)tok * WD;
            st4h(g_flat + fl + 2 * DIM + f0, base);
            st4h(g_flat + fl + 3 * DIM + f0, r1);
            st4h(g_flat + fl + 4 * DIM + f0, r2);
            float4 nr2;
            nr2.x = w * r1.x + c * r2.x; nr2.y = w * r1.y + c * r2.y;
            nr2.z = w * r1.z + c * r2.z; nr2.w = w * r1.w + c * r2.w;
            r1.x = w * base.x + c * r1.x; r1.y = w * base.y + c * r1.y;
            r1.z = w * base.z + c * r1.z; r1.w = w * base.w + c * r1.w;
            r2 = nr2;
        }
    }
}

// ---------------- per-step kernels ----------------
// combine: sv read from fp32 g_seq (exact blend path); lc from fp16 cc
__global__ void combine_kernel(const float* __restrict__ lng, const float* __restrict__ lnb) {
    int tok = blockIdx.x, f = threadIdx.x;
    const float* ct = g_contents + (size_t)tok * HID;
    size_t cp = (size_t)tok * 2 * DIM;
    float lc = __half2float(g_cc[cp + f]);
    float sv = g_seq[(size_t)tok * DIM + f];
    float g0 = 1.f / (1.f + expf(-ct[0 * DIM + f]));
    float g1 = 1.f / (1.f + expf(-ct[1 * DIM + f]));
    float g2 = 1.f / (1.f + expf(-ct[2 * DIM + f]));
    float y = g0 * lc + g1 * sv + g2 * ct[3 * DIM + f];
    float mean = blockReduceSum256(y) * (1.f / DIM);
    float d = y - mean;
    float r = rsqrtf(blockReduceSum256(d * d) * (1.f / DIM) + 1e-5f);
    float comp = d * r * lng[f] + lnb[f];
    float mx = g_mx;
    float et = expf(g_tsc[tok] - mx) * g_selp[tok];
    float tp = et / (et + expf(-mx) + EPSF);
    if (f == 0) g_tp[tok] = tp;
    g_seq[(size_t)tok * DIM + f] = (tp * comp + (1.f - tp) * sv) * g_mask[tok];
}

__global__ void deact_kernel() {
    __shared__ float s_a[S2], s_m[S2], s_tp[S2];
    int b = blockIdx.x;
    if (b == 0 && threadIdx.x == 0) g_mx = 0.f;   // reset for next step's score
    for (int i = threadIdx.x; i < S2; i += blockDim.x) {
        int tok = b * S2 + i;
        s_a[i] = g_active[tok]; s_m[i] = g_mask[tok]; s_tp[i] = g_tp[tok];
    }
    __syncthreads();
    if (threadIdx.x == 0) {
        float dacc = 0.f;
        for (int j = S2 - 1; j >= 0; j--) {
            float a = s_a[j], m = s_m[j], tp = s_tp[j];
            float de = a * m * m * dacc;
            s_a[j] = fminf(fmaxf(a * (1.f - de), 0.f), 1.f) * m;
            dacc = tp + (1.f - a * m + EPSF) * dacc;
        }
    }
    __syncthreads();
    for (int i = threadIdx.x; i < S2; i += blockDim.x) {
        int tok = b * S2 + i;
        g_active[tok] = s_a[i];
        g_ltp[tok]    = s_tp[i];
    }
}

__global__ void copy_out_kernel(float* __restrict__ out) {
    int idx = blockIdx.x * blockDim.x + threadIdx.x;
    if (idx < NTOK * DIM) out[idx] = g_seq[idx];
}

// ---------------- launch ----------------
extern "C" void kernel_launch(void* const* d_in, const int* in_sizes, int n_in,
                              void* d_out, int out_size) {
    const float* sequence   = (const float*)d_in[0];
    const float* input_mask = (const float*)d_in[1];
    const float* START = (const float*)d_in[2];
    const float* END   = (const float*)d_in[3];
    const float* yes_t = (const float*)d_in[4];
    const float* no_t  = (const float*)d_in[5];
    const float* convW = (const float*)d_in[6];
    const float* convb = (const float*)d_in[7];
    const float* scW   = (const float*)d_in[8];
    const float* scb   = (const float*)d_in[9];
    const float* itW   = (const float*)d_in[10];
    const float* itb   = (const float*)d_in[11];
    const float* w1W   = (const float*)d_in[12];
    const float* w1b   = (const float*)d_in[13];
    const float* w2W   = (const float*)d_in[14];
    const float* w2b   = (const float*)d_in[15];
    const float* lng   = (const float*)d_in[16];
    const float* lnb   = (const float*)d_in[17];
    float* out = (float*)d_out;

    __half *p_flat, *p_cc, *p_inter, *p_convWt, *p_w1Wt, *p_w2Wt, *p_itWt;
    float *p_contents, *p_convOut;
    cudaGetSymbolAddress((void**)&p_flat, g_flat);
    cudaGetSymbolAddress((void**)&p_cc, g_cc);
    cudaGetSymbolAddress((void**)&p_inter, g_inter);
    cudaGetSymbolAddress((void**)&p_contents, g_contents);
    cudaGetSymbolAddress((void**)&p_convOut, g_convOut);
    cudaGetSymbolAddress((void**)&p_convWt, g_convWt);
    cudaGetSymbolAddress((void**)&p_w1Wt, g_w1Wt);
    cudaGetSymbolAddress((void**)&p_w2Wt, g_w2Wt);
    cudaGetSymbolAddress((void**)&p_itWt, g_itWt);

    const int SMEMB = 2 * STG_BYTES;   // 110592
    cudaFuncSetAttribute(mma_gemm<0,0,0>, cudaFuncAttributeMaxDynamicSharedMemorySize, SMEMB);
    cudaFuncSetAttribute(mma_gemm<1,1,0>, cudaFuncAttributeMaxDynamicSharedMemorySize, SMEMB);
    cudaFuncSetAttribute(mma_gemm<1,0,1>, cudaFuncAttributeMaxDynamicSharedMemorySize, SMEMB);

    const int THR = 256;
    const int GM = (NTOK + 127) / 128;   // 129

    init_masks_kernel<<<(NTOK + THR - 1) / THR, THR>>>(input_mask);
    init_seqpre_kernel<<<(NTOK * DIM + THR - 1) / THR, THR>>>(sequence, START, END);
    pack_weightT<<<(DIM * DIM + THR - 1) / THR, THR>>>(itW, p_itWt, DIM, DIM);
    pack_weightT<<<(DIM * WD + THR - 1) / THR, THR>>>(convW, p_convWt, WD, DIM);
    pack_w1w2<<<(HID * 2 * DIM + HID * HID + THR - 1) / THR, THR>>>(
        w1W, p_w1Wt, w2W, p_w2Wt);

    // grid: x = N-tiles (fast-varying, shares A tile), y = M-tiles
    mma_gemm<0,0,0><<<dim3(1, GM), 512, SMEMB>>>(p_cc, 2 * DIM,
        p_itWt, itb, p_convOut, DIM, NTOK, DIM, nullptr, nullptr);
    ln_init_kernel<<<NTOK, DIM>>>(lng, lnb);

    for (int s = 0; s < NSTEPS; s++) {
        scan_kernel<<<(2 * NB * 64 + THR - 1) / THR, THR>>>(yes_t, no_t);
        mma_gemm<1,0,1><<<dim3(1, GM), 512, SMEMB>>>(p_flat, WD,
            p_convWt, convb, nullptr, DIM, NTOK, WD, scW, scb);
        mma_gemm<1,1,0><<<dim3(4, GM), 512, SMEMB>>>(p_cc, 2 * DIM,
            p_w1Wt, w1b, p_inter, HID, NTOK, 2 * DIM, nullptr, nullptr);
        mma_gemm<0,0,0><<<dim3(4, GM), 512, SMEMB>>>(p_inter, HID,
            p_w2Wt, w2b, p_contents, HID, NTOK, HID, nullptr, nullptr);
        combine_kernel<<<NTOK, DIM>>>(lng, lnb);
        deact_kernel<<<NB, 128>>>();
    }

    copy_out_kernel<<<(NTOK * DIM + THR - 1) / THR, THR>>>(out);
}